// round 5
// baseline (speedup 1.0000x reference)
#include <cuda_runtime.h>
#include <cuda_bf16.h>
#include <cstdint>
#include <cstring>

// ---------------------------------------------------------------------------
// CLOPLayer: out[b,c,j] = x[b,c,perm[j]], perm = fixed JAX threefry(42)
// neighbor-swap permutation, computed bit-exactly on the host and passed as a
// 28KB __grid_constant__ kernel parameter (no device allocations, no second
// kernel, no memcpy). Single-kernel graph: avoids the per-replay L1/SMEM
// carveout reconfiguration that the two-kernel version paid.
// Gather: cp.async double-buffered row pipeline; row r+1 streams GMEM->SMEM
// (LDGSTS.cg) while row r is scattered from SMEM (stride-1 conflict-free LDS)
// to coalesced streaming stores. 576 CTAs x 8 rows = 4608 rows, one wave.
// ---------------------------------------------------------------------------

#define N_ELEM 7056            // 84*84
#define DIM    84
#define NVEC   (N_ELEM / 4)    // 1764
#define NTHR   512
#define COLS_PER_THR 14        // ceil(7056/512)
#define VECS_PER_THR 4         // ceil(1764/512)
#define ROWS_PER_BLK 8

struct PermArg { int v[N_ELEM]; };

__device__ __forceinline__ void cp_async16(uint32_t saddr, const void* g) {
    asm volatile("cp.async.cg.shared.global [%0], [%1], 16;\n"
                 :: "r"(saddr), "l"(g) : "memory");
}
__device__ __forceinline__ void cp_commit() {
    asm volatile("cp.async.commit_group;\n" ::: "memory");
}
template <int N>
__device__ __forceinline__ void cp_wait() {
    asm volatile("cp.async.wait_group %0;\n" :: "n"(N) : "memory");
}

__device__ __forceinline__ void load_row_async(
    uint32_t buf_saddr, const float* __restrict__ xrow, int t)
{
    #pragma unroll
    for (int k = 0; k < VECS_PER_THR; ++k) {
        int v = t + k * NTHR;
        if (v < NVEC) {
            cp_async16(buf_saddr + (uint32_t)v * 16u,
                       reinterpret_cast<const float4*>(xrow) + v);
        }
    }
    cp_commit();
}

extern __shared__ float s_buf[];   // 2 * N_ELEM floats = 56448 B

__global__ __launch_bounds__(NTHR) void clop_gather_kernel(
    const float* __restrict__ x, float* __restrict__ out, int nrows,
    const __grid_constant__ PermArg perm)
{
    const int t = threadIdx.x;
    const int r0 = blockIdx.x * ROWS_PER_BLK;

    float* buf0 = s_buf;
    float* buf1 = s_buf + N_ELEM;
    uint32_t sa0, sa1;
    asm("{ .reg .u64 a; cvta.to.shared.u64 a, %1; cvt.u32.u64 %0, a; }"
        : "=r"(sa0) : "l"(buf0));
    sa1 = sa0 + N_ELEM * 4u;

    // prologue: start loading row r0 into buf0 ASAP
    if (r0 < nrows)
        load_row_async(sa0, x + (size_t)r0 * N_ELEM, t);

    // perm values for this thread's columns, in registers for all rows
    // (LDC from the kernel-param constant bank; once per block)
    int pc[COLS_PER_THR];
    #pragma unroll
    for (int k = 0; k < COLS_PER_THR; ++k) {
        int col = t + k * NTHR;
        pc[k] = (col < N_ELEM) ? perm.v[col] : 0;
    }

    #pragma unroll
    for (int r = 0; r < ROWS_PER_BLK; ++r) {
        int row = r0 + r;
        if (row >= nrows) break;

        float* cur = (r & 1) ? buf1 : buf0;

        // issue next row's loads into the other buffer, then wait for current
        int nrow = row + 1;
        if (r + 1 < ROWS_PER_BLK && nrow < nrows) {
            uint32_t na = (r & 1) ? sa0 : sa1;
            load_row_async(na, x + (size_t)nrow * N_ELEM, t);
            cp_wait<1>();     // current row's group complete; next may fly
        } else {
            cp_wait<0>();
        }
        __syncthreads();

        // permuted read from smem (stride-1 => conflict-free), coalesced
        // streaming scalar stores
        float* dst = out + (size_t)row * N_ELEM;
        #pragma unroll
        for (int k = 0; k < COLS_PER_THR; ++k) {
            int col = t + k * NTHR;
            if (col < N_ELEM) __stcs(dst + col, cur[pc[k]]);
        }
        __syncthreads();  // all reads of 'cur' done before it is refilled
    }
}

// ---------------------------------------------------------------------------
// Host-side bit-exact JAX RNG replication (threefry2x32, partitionable path)
// ---------------------------------------------------------------------------

static inline uint32_t rotl32(uint32_t v, int r) {
    return (v << r) | (v >> (32 - r));
}

static inline void threefry2x32(uint32_t k0, uint32_t k1,
                                uint32_t& x0, uint32_t& x1)
{
    const uint32_t ks0 = k0;
    const uint32_t ks1 = k1;
    const uint32_t ks2 = k0 ^ k1 ^ 0x1BD11BDAu;
    const int ra[4] = {13, 15, 26, 6};
    const int rb[4] = {17, 29, 16, 24};

    x0 += ks0; x1 += ks1;
    for (int i = 0; i < 4; i++) { x0 += x1; x1 = rotl32(x1, ra[i]); x1 ^= x0; }
    x0 += ks1; x1 += ks2 + 1u;
    for (int i = 0; i < 4; i++) { x0 += x1; x1 = rotl32(x1, rb[i]); x1 ^= x0; }
    x0 += ks2; x1 += ks0 + 2u;
    for (int i = 0; i < 4; i++) { x0 += x1; x1 = rotl32(x1, ra[i]); x1 ^= x0; }
    x0 += ks0; x1 += ks1 + 3u;
    for (int i = 0; i < 4; i++) { x0 += x1; x1 = rotl32(x1, rb[i]); x1 ^= x0; }
    x0 += ks1; x1 += ks2 + 4u;
    for (int i = 0; i < 4; i++) { x0 += x1; x1 = rotl32(x1, ra[i]); x1 ^= x0; }
    x0 += ks2; x1 += ks0 + 5u;
}

static inline uint32_t jax_random_bits32(uint32_t k0, uint32_t k1, uint64_t i) {
    uint32_t x0 = (uint32_t)(i >> 32);
    uint32_t x1 = (uint32_t)(i & 0xFFFFFFFFu);
    threefry2x32(k0, k1, x0, x1);
    return x0 ^ x1;
}

static void compute_perm(int* perm) {
    const int n = N_ELEM;
    const int dim = DIM;
    const int steps = 2 * n - 1;   // 14111

    float probs[5];
    probs[0] = (float)(1.0 - 0.9 / 2.0);
    for (int q = 1; q < 5; q++) probs[q] = (float)(0.9 / 8.0);
    float pc[5];
    pc[0] = probs[0];
    for (int q = 1; q < 5; q++) pc[q] = pc[q - 1] + probs[q];

    const int offsets[5] = {0, 1, -1, dim, -dim};

    for (int t = 0; t < n; t++) perm[t] = t;

    const uint32_t k0 = 0u, k1 = 42u;   // jax.random.key(42)

    for (int s = 0; s < steps; s++) {
        int i = s - (n - 1);
        if (i < 0) i = -i;

        uint32_t bits = jax_random_bits32(k0, k1, (uint64_t)s);
        uint32_t fb = (bits >> 9) | 0x3F800000u;
        float u;
        memcpy(&u, &fb, 4);
        u -= 1.0f;

        float rv = pc[4] * (1.0f - u);
        int ind = 0;
        while (ind < 5 && pc[ind] < rv) ind++;
        if (ind > 4) ind = 4;

        int idx = i + offsets[ind];
        if (ind != 0 && idx > 0 && idx < n) {
            int a = perm[i];
            perm[i] = perm[idx];
            perm[idx] = a;
        }
    }
}

// ---------------------------------------------------------------------------

extern "C" void kernel_launch(void* const* d_in, const int* in_sizes, int n_in,
                              void* d_out, int out_size) {
    const float* x = (const float*)d_in[0];
    float* out = (float*)d_out;
    int total = in_sizes[0];
    int nrows = total / N_ELEM;    // 512*9 = 4608

    static PermArg parg;           // storage only; recomputed every call
    compute_perm(parg.v);

    const int smem_bytes = 2 * N_ELEM * (int)sizeof(float);   // 56448
    cudaFuncSetAttribute(clop_gather_kernel,
                         cudaFuncAttributeMaxDynamicSharedMemorySize,
                         smem_bytes);

    int nblk = (nrows + ROWS_PER_BLK - 1) / ROWS_PER_BLK;   // 576
    clop_gather_kernel<<<nblk, NTHR, smem_bytes>>>(x, out, nrows, parg);
}

// round 6
// speedup vs baseline: 1.3790x; 1.3790x over previous
#include <cuda_runtime.h>
#include <cuda_bf16.h>
#include <cstdint>

// ---------------------------------------------------------------------------
// CLOPLayer: out[b,c,j] = x[b,c,perm[j]], perm = fixed JAX threefry(42)
// neighbor-swap permutation. The permutation depends only on compile-time
// constants, so it is evaluated entirely at COMPILE TIME via constexpr and
// baked into a __device__ global (module .data). No unpack kernel, no 28KB
// kernel param, no divergent LDC, no H2D copy. Single-kernel graph.
// Gather: cp.async double-buffered row pipeline; row r+1 streams GMEM->SMEM
// (LDGSTS.cg) while row r is scattered from SMEM (stride-1 conflict-free LDS)
// to coalesced streaming stores. 576 CTAs x 8 rows = 4608 rows, one wave.
// ---------------------------------------------------------------------------

#define N_ELEM 7056            // 84*84
#define DIM    84
#define NVEC   (N_ELEM / 4)    // 1764
#define NTHR   512
#define COLS_PER_THR 14        // ceil(7056/512)
#define VECS_PER_THR 4         // ceil(1764/512)
#define ROWS_PER_BLK 8

// ---------------------------------------------------------------------------
// Compile-time bit-exact JAX RNG replication (threefry2x32, partitionable)
// ---------------------------------------------------------------------------

struct PermTable { int v[N_ELEM]; };

constexpr uint32_t rotl32c(uint32_t v, int r) {
    return (v << r) | (v >> (32 - r));
}

struct TF2 { uint32_t x0, x1; };

constexpr TF2 threefry2x32c(uint32_t k0, uint32_t k1, uint32_t x0, uint32_t x1) {
    const uint32_t ks0 = k0;
    const uint32_t ks1 = k1;
    const uint32_t ks2 = k0 ^ k1 ^ 0x1BD11BDAu;
    const int ra[4] = {13, 15, 26, 6};
    const int rb[4] = {17, 29, 16, 24};

    x0 += ks0; x1 += ks1;
    for (int i = 0; i < 4; i++) { x0 += x1; x1 = rotl32c(x1, ra[i]); x1 ^= x0; }
    x0 += ks1; x1 += ks2 + 1u;
    for (int i = 0; i < 4; i++) { x0 += x1; x1 = rotl32c(x1, rb[i]); x1 ^= x0; }
    x0 += ks2; x1 += ks0 + 2u;
    for (int i = 0; i < 4; i++) { x0 += x1; x1 = rotl32c(x1, ra[i]); x1 ^= x0; }
    x0 += ks0; x1 += ks1 + 3u;
    for (int i = 0; i < 4; i++) { x0 += x1; x1 = rotl32c(x1, rb[i]); x1 ^= x0; }
    x0 += ks1; x1 += ks2 + 4u;
    for (int i = 0; i < 4; i++) { x0 += x1; x1 = rotl32c(x1, ra[i]); x1 ^= x0; }
    x0 += ks2; x1 += ks0 + 5u;
    return TF2{x0, x1};
}

constexpr uint32_t jax_bits32c(uint32_t k0, uint32_t k1, uint64_t i) {
    TF2 r = threefry2x32c(k0, k1, (uint32_t)(i >> 32), (uint32_t)(i & 0xFFFFFFFFu));
    return r.x0 ^ r.x1;
}

constexpr PermTable make_perm() {
    PermTable p{};
    const int n = N_ELEM;
    const int dim = DIM;
    const int steps = 2 * n - 1;   // 14111

    float probs0 = (float)(1.0 - 0.9 / 2.0);
    float probsq = (float)(0.9 / 8.0);
    float pc[5] = {};
    pc[0] = probs0;
    for (int q = 1; q < 5; q++) pc[q] = pc[q - 1] + probsq;

    const int offsets[5] = {0, 1, -1, dim, -dim};

    for (int t = 0; t < n; t++) p.v[t] = t;

    const uint32_t k0 = 0u, k1 = 42u;   // jax.random.key(42)

    for (int s = 0; s < steps; s++) {
        int i = s - (n - 1);
        if (i < 0) i = -i;

        uint32_t bits = jax_bits32c(k0, k1, (uint64_t)s);
        // u = bitcast(bits>>9 | 0x3F800000) - 1.0f  ==  (float)(bits>>9) * 2^-23
        // (both exact: mantissa < 2^23, power-of-two scale, exact subtraction)
        float u = (float)(bits >> 9) * (1.0f / 8388608.0f);

        float rv = pc[4] * (1.0f - u);
        int ind = 0;
        while (ind < 5 && pc[ind] < rv) ind++;
        if (ind > 4) ind = 4;

        int idx = i + offsets[ind];
        if (ind != 0 && idx > 0 && idx < n) {
            int a = p.v[i];
            p.v[i] = p.v[idx];
            p.v[idx] = a;
        }
    }
    return p;
}

// Baked into the cubin's .data at compile time; loaded with the module.
__device__ constexpr PermTable g_perm = make_perm();

// ---------------------------------------------------------------------------

__device__ __forceinline__ void cp_async16(uint32_t saddr, const void* g) {
    asm volatile("cp.async.cg.shared.global [%0], [%1], 16;\n"
                 :: "r"(saddr), "l"(g) : "memory");
}
__device__ __forceinline__ void cp_commit() {
    asm volatile("cp.async.commit_group;\n" ::: "memory");
}
template <int N>
__device__ __forceinline__ void cp_wait() {
    asm volatile("cp.async.wait_group %0;\n" :: "n"(N) : "memory");
}

__device__ __forceinline__ void load_row_async(
    uint32_t buf_saddr, const float* __restrict__ xrow, int t)
{
    #pragma unroll
    for (int k = 0; k < VECS_PER_THR; ++k) {
        int v = t + k * NTHR;
        if (v < NVEC) {
            cp_async16(buf_saddr + (uint32_t)v * 16u,
                       reinterpret_cast<const float4*>(xrow) + v);
        }
    }
    cp_commit();
}

extern __shared__ float s_buf[];   // 2 * N_ELEM floats = 56448 B

__global__ __launch_bounds__(NTHR) void clop_gather_kernel(
    const float* __restrict__ x, float* __restrict__ out, int nrows)
{
    const int t = threadIdx.x;
    const int r0 = blockIdx.x * ROWS_PER_BLK;

    float* buf0 = s_buf;
    uint32_t sa0, sa1;
    asm("{ .reg .u64 a; cvta.to.shared.u64 a, %1; cvt.u32.u64 %0, a; }"
        : "=r"(sa0) : "l"(buf0));
    sa1 = sa0 + N_ELEM * 4u;
    float* buf1 = s_buf + N_ELEM;

    // prologue: start loading row r0 ASAP so perm LDGs overlap its latency
    if (r0 < nrows)
        load_row_async(sa0, x + (size_t)r0 * N_ELEM, t);

    // perm values for this thread's columns (coalesced LDG, once per block)
    const int* __restrict__ pg = g_perm.v;
    int pc[COLS_PER_THR];
    #pragma unroll
    for (int k = 0; k < COLS_PER_THR; ++k) {
        int col = t + k * NTHR;
        pc[k] = (col < N_ELEM) ? __ldg(pg + col) : 0;
    }

    #pragma unroll
    for (int r = 0; r < ROWS_PER_BLK; ++r) {
        int row = r0 + r;
        if (row >= nrows) break;

        float* cur = (r & 1) ? buf1 : buf0;

        // issue next row's loads into the other buffer, then wait for current
        int nrow = row + 1;
        if (r + 1 < ROWS_PER_BLK && nrow < nrows) {
            uint32_t na = (r & 1) ? sa0 : sa1;
            load_row_async(na, x + (size_t)nrow * N_ELEM, t);
            cp_wait<1>();     // current row's group complete; next may fly
        } else {
            cp_wait<0>();
        }
        __syncthreads();

        // permuted read from smem (stride-1 => conflict-free), coalesced
        // streaming scalar stores
        float* dst = out + (size_t)row * N_ELEM;
        #pragma unroll
        for (int k = 0; k < COLS_PER_THR; ++k) {
            int col = t + k * NTHR;
            if (col < N_ELEM) __stcs(dst + col, cur[pc[k]]);
        }
        __syncthreads();  // all reads of 'cur' done before it is refilled
    }
}

// ---------------------------------------------------------------------------

extern "C" void kernel_launch(void* const* d_in, const int* in_sizes, int n_in,
                              void* d_out, int out_size) {
    const float* x = (const float*)d_in[0];
    float* out = (float*)d_out;
    int total = in_sizes[0];
    int nrows = total / N_ELEM;    // 512*9 = 4608

    const int smem_bytes = 2 * N_ELEM * (int)sizeof(float);   // 56448
    cudaFuncSetAttribute(clop_gather_kernel,
                         cudaFuncAttributeMaxDynamicSharedMemorySize,
                         smem_bytes);

    int nblk = (nrows + ROWS_PER_BLK - 1) / ROWS_PER_BLK;   // 576
    clop_gather_kernel<<<nblk, NTHR, smem_bytes>>>(x, out, nrows);
}

// round 7
// speedup vs baseline: 1.4065x; 1.0200x over previous
#include <cuda_runtime.h>
#include <cuda_bf16.h>
#include <cstdint>

// ---------------------------------------------------------------------------
// CLOPLayer: out[b,c,j] = x[b,c,perm[j]], perm = fixed JAX threefry(42)
// neighbor-swap permutation, evaluated at COMPILE TIME (constexpr) and baked
// into module .data. Single-kernel graph.
// Wall time is DRAM-traffic-bound (260MB/replay @ ~5.3TB/s sustained). This
// round: pin ~85% of x's lines in L2 via a fractional evict_last access
// policy on the cp.async loads (x = 130MB vs 126MB L2; the pinned ~110MB
// subset survives across graph replays), writes stay evict_first streaming.
// Steady-state DRAM traffic drops toward ~150MB/replay.
// Gather: cp.async double-buffered row pipeline; stride-1 conflict-free LDS
// scatter; coalesced streaming stores. 576 CTAs x 8 rows, one wave.
// ---------------------------------------------------------------------------

#define N_ELEM 7056            // 84*84
#define DIM    84
#define NVEC   (N_ELEM / 4)    // 1764
#define NTHR   512
#define COLS_PER_THR 14        // ceil(7056/512)
#define VECS_PER_THR 4         // ceil(1764/512)
#define ROWS_PER_BLK 8

// ---------------------------------------------------------------------------
// Compile-time bit-exact JAX RNG replication (threefry2x32, partitionable)
// ---------------------------------------------------------------------------

struct PermTable { int v[N_ELEM]; };

constexpr uint32_t rotl32c(uint32_t v, int r) {
    return (v << r) | (v >> (32 - r));
}

struct TF2 { uint32_t x0, x1; };

constexpr TF2 threefry2x32c(uint32_t k0, uint32_t k1, uint32_t x0, uint32_t x1) {
    const uint32_t ks0 = k0;
    const uint32_t ks1 = k1;
    const uint32_t ks2 = k0 ^ k1 ^ 0x1BD11BDAu;
    const int ra[4] = {13, 15, 26, 6};
    const int rb[4] = {17, 29, 16, 24};

    x0 += ks0; x1 += ks1;
    for (int i = 0; i < 4; i++) { x0 += x1; x1 = rotl32c(x1, ra[i]); x1 ^= x0; }
    x0 += ks1; x1 += ks2 + 1u;
    for (int i = 0; i < 4; i++) { x0 += x1; x1 = rotl32c(x1, rb[i]); x1 ^= x0; }
    x0 += ks2; x1 += ks0 + 2u;
    for (int i = 0; i < 4; i++) { x0 += x1; x1 = rotl32c(x1, ra[i]); x1 ^= x0; }
    x0 += ks0; x1 += ks1 + 3u;
    for (int i = 0; i < 4; i++) { x0 += x1; x1 = rotl32c(x1, rb[i]); x1 ^= x0; }
    x0 += ks1; x1 += ks2 + 4u;
    for (int i = 0; i < 4; i++) { x0 += x1; x1 = rotl32c(x1, ra[i]); x1 ^= x0; }
    x0 += ks2; x1 += ks0 + 5u;
    return TF2{x0, x1};
}

constexpr uint32_t jax_bits32c(uint32_t k0, uint32_t k1, uint64_t i) {
    TF2 r = threefry2x32c(k0, k1, (uint32_t)(i >> 32), (uint32_t)(i & 0xFFFFFFFFu));
    return r.x0 ^ r.x1;
}

constexpr PermTable make_perm() {
    PermTable p{};
    const int n = N_ELEM;
    const int dim = DIM;
    const int steps = 2 * n - 1;   // 14111

    float probs0 = (float)(1.0 - 0.9 / 2.0);
    float probsq = (float)(0.9 / 8.0);
    float pc[5] = {};
    pc[0] = probs0;
    for (int q = 1; q < 5; q++) pc[q] = pc[q - 1] + probsq;

    const int offsets[5] = {0, 1, -1, dim, -dim};

    for (int t = 0; t < n; t++) p.v[t] = t;

    const uint32_t k0 = 0u, k1 = 42u;   // jax.random.key(42)

    for (int s = 0; s < steps; s++) {
        int i = s - (n - 1);
        if (i < 0) i = -i;

        uint32_t bits = jax_bits32c(k0, k1, (uint64_t)s);
        // u = bitcast(bits>>9 | 0x3F800000) - 1.0f == (float)(bits>>9) * 2^-23
        float u = (float)(bits >> 9) * (1.0f / 8388608.0f);

        float rv = pc[4] * (1.0f - u);
        int ind = 0;
        while (ind < 5 && pc[ind] < rv) ind++;
        if (ind > 4) ind = 4;

        int idx = i + offsets[ind];
        if (ind != 0 && idx > 0 && idx < n) {
            int a = p.v[i];
            p.v[i] = p.v[idx];
            p.v[idx] = a;
        }
    }
    return p;
}

__device__ constexpr PermTable g_perm = make_perm();

// ---------------------------------------------------------------------------

__device__ __forceinline__ uint64_t mk_policy_evict_last() {
    uint64_t pol;
    // 85% of accessed lines -> evict_last (persist across replays),
    // remainder -> evict_first (don't fight for capacity).
    asm("createpolicy.fractional.L2::evict_last.L2::evict_first.b64 %0, 0.85;"
        : "=l"(pol));
    return pol;
}

__device__ __forceinline__ void cp_async16_pol(uint32_t saddr, const void* g,
                                               uint64_t pol) {
    asm volatile("cp.async.cg.shared.global.L2::cache_hint [%0], [%1], 16, %2;\n"
                 :: "r"(saddr), "l"(g), "l"(pol) : "memory");
}
__device__ __forceinline__ void cp_commit() {
    asm volatile("cp.async.commit_group;\n" ::: "memory");
}
template <int N>
__device__ __forceinline__ void cp_wait() {
    asm volatile("cp.async.wait_group %0;\n" :: "n"(N) : "memory");
}

__device__ __forceinline__ void load_row_async(
    uint32_t buf_saddr, const float* __restrict__ xrow, int t, uint64_t pol)
{
    #pragma unroll
    for (int k = 0; k < VECS_PER_THR; ++k) {
        int v = t + k * NTHR;
        if (v < NVEC) {
            cp_async16_pol(buf_saddr + (uint32_t)v * 16u,
                           reinterpret_cast<const float4*>(xrow) + v, pol);
        }
    }
    cp_commit();
}

extern __shared__ float s_buf[];   // 2 * N_ELEM floats = 56448 B

__global__ __launch_bounds__(NTHR) void clop_gather_kernel(
    const float* __restrict__ x, float* __restrict__ out, int nrows)
{
    const int t = threadIdx.x;
    const int r0 = blockIdx.x * ROWS_PER_BLK;
    const uint64_t pol = mk_policy_evict_last();

    float* buf0 = s_buf;
    uint32_t sa0, sa1;
    asm("{ .reg .u64 a; cvta.to.shared.u64 a, %1; cvt.u32.u64 %0, a; }"
        : "=r"(sa0) : "l"(buf0));
    sa1 = sa0 + N_ELEM * 4u;
    float* buf1 = s_buf + N_ELEM;

    // prologue: start loading row r0 ASAP so perm LDGs overlap its latency
    if (r0 < nrows)
        load_row_async(sa0, x + (size_t)r0 * N_ELEM, t, pol);

    // perm values for this thread's columns (coalesced LDG, once per block)
    const int* __restrict__ pg = g_perm.v;
    int pc[COLS_PER_THR];
    #pragma unroll
    for (int k = 0; k < COLS_PER_THR; ++k) {
        int col = t + k * NTHR;
        pc[k] = (col < N_ELEM) ? __ldg(pg + col) : 0;
    }

    #pragma unroll
    for (int r = 0; r < ROWS_PER_BLK; ++r) {
        int row = r0 + r;
        if (row >= nrows) break;

        float* cur = (r & 1) ? buf1 : buf0;

        // issue next row's loads into the other buffer, then wait for current
        int nrow = row + 1;
        if (r + 1 < ROWS_PER_BLK && nrow < nrows) {
            uint32_t na = (r & 1) ? sa0 : sa1;
            load_row_async(na, x + (size_t)nrow * N_ELEM, t, pol);
            cp_wait<1>();     // current row's group complete; next may fly
        } else {
            cp_wait<0>();
        }
        __syncthreads();

        // permuted read from smem (stride-1 => conflict-free), coalesced
        // streaming (evict_first) scalar stores
        float* dst = out + (size_t)row * N_ELEM;
        #pragma unroll
        for (int k = 0; k < COLS_PER_THR; ++k) {
            int col = t + k * NTHR;
            if (col < N_ELEM) __stcs(dst + col, cur[pc[k]]);
        }
        __syncthreads();  // all reads of 'cur' done before it is refilled
    }
}

// ---------------------------------------------------------------------------

extern "C" void kernel_launch(void* const* d_in, const int* in_sizes, int n_in,
                              void* d_out, int out_size) {
    const float* x = (const float*)d_in[0];
    float* out = (float*)d_out;
    int total = in_sizes[0];
    int nrows = total / N_ELEM;    // 512*9 = 4608

    const int smem_bytes = 2 * N_ELEM * (int)sizeof(float);   // 56448
    cudaFuncSetAttribute(clop_gather_kernel,
                         cudaFuncAttributeMaxDynamicSharedMemorySize,
                         smem_bytes);

    int nblk = (nrows + ROWS_PER_BLK - 1) / ROWS_PER_BLK;   // 576
    clop_gather_kernel<<<nblk, NTHR, smem_bytes>>>(x, out, nrows);
}

// round 8
// speedup vs baseline: 1.4217x; 1.0108x over previous
#include <cuda_runtime.h>
#include <cuda_bf16.h>
#include <cstdint>

// ---------------------------------------------------------------------------
// CLOPLayer: out[b,c,j] = x[b,c,perm[j]], perm = fixed JAX threefry(42)
// neighbor-swap permutation, evaluated at COMPILE TIME (constexpr) and baked
// into module .data. Single-kernel graph.
// Wall is DRAM-traffic-bound (260MB/replay, sustained ~5.4TB/s). This round:
// 4-stage cp.async row pipeline (prefetch depth 3) -> 169KB in-flight reads
// per SM (vs 113KB), smoothing the read stream to raise sustained mixed BW.
// 288 CTAs x 16 rows = 4608 exact; 2 CTAs/SM (112.9KB smem each), one wave.
// Scatter: stride-1 conflict-free LDS, coalesced streaming stores.
// ---------------------------------------------------------------------------

#define N_ELEM 7056            // 84*84
#define DIM    84
#define NVEC   (N_ELEM / 4)    // 1764
#define NTHR   512
#define COLS_PER_THR 14        // ceil(7056/512)
#define VECS_PER_THR 4         // ceil(1764/512)
#define ROWS_PER_BLK 16
#define NSTAGE 4

// ---------------------------------------------------------------------------
// Compile-time bit-exact JAX RNG replication (threefry2x32, partitionable)
// ---------------------------------------------------------------------------

struct PermTable { int v[N_ELEM]; };

constexpr uint32_t rotl32c(uint32_t v, int r) {
    return (v << r) | (v >> (32 - r));
}

struct TF2 { uint32_t x0, x1; };

constexpr TF2 threefry2x32c(uint32_t k0, uint32_t k1, uint32_t x0, uint32_t x1) {
    const uint32_t ks0 = k0;
    const uint32_t ks1 = k1;
    const uint32_t ks2 = k0 ^ k1 ^ 0x1BD11BDAu;
    const int ra[4] = {13, 15, 26, 6};
    const int rb[4] = {17, 29, 16, 24};

    x0 += ks0; x1 += ks1;
    for (int i = 0; i < 4; i++) { x0 += x1; x1 = rotl32c(x1, ra[i]); x1 ^= x0; }
    x0 += ks1; x1 += ks2 + 1u;
    for (int i = 0; i < 4; i++) { x0 += x1; x1 = rotl32c(x1, rb[i]); x1 ^= x0; }
    x0 += ks2; x1 += ks0 + 2u;
    for (int i = 0; i < 4; i++) { x0 += x1; x1 = rotl32c(x1, ra[i]); x1 ^= x0; }
    x0 += ks0; x1 += ks1 + 3u;
    for (int i = 0; i < 4; i++) { x0 += x1; x1 = rotl32c(x1, rb[i]); x1 ^= x0; }
    x0 += ks1; x1 += ks2 + 4u;
    for (int i = 0; i < 4; i++) { x0 += x1; x1 = rotl32c(x1, ra[i]); x1 ^= x0; }
    x0 += ks2; x1 += ks0 + 5u;
    return TF2{x0, x1};
}

constexpr uint32_t jax_bits32c(uint32_t k0, uint32_t k1, uint64_t i) {
    TF2 r = threefry2x32c(k0, k1, (uint32_t)(i >> 32), (uint32_t)(i & 0xFFFFFFFFu));
    return r.x0 ^ r.x1;
}

constexpr PermTable make_perm() {
    PermTable p{};
    const int n = N_ELEM;
    const int dim = DIM;
    const int steps = 2 * n - 1;   // 14111

    float probs0 = (float)(1.0 - 0.9 / 2.0);
    float probsq = (float)(0.9 / 8.0);
    float pc[5] = {};
    pc[0] = probs0;
    for (int q = 1; q < 5; q++) pc[q] = pc[q - 1] + probsq;

    const int offsets[5] = {0, 1, -1, dim, -dim};

    for (int t = 0; t < n; t++) p.v[t] = t;

    const uint32_t k0 = 0u, k1 = 42u;   // jax.random.key(42)

    for (int s = 0; s < steps; s++) {
        int i = s - (n - 1);
        if (i < 0) i = -i;

        uint32_t bits = jax_bits32c(k0, k1, (uint64_t)s);
        // u = bitcast(bits>>9 | 0x3F800000) - 1.0f == (float)(bits>>9) * 2^-23
        float u = (float)(bits >> 9) * (1.0f / 8388608.0f);

        float rv = pc[4] * (1.0f - u);
        int ind = 0;
        while (ind < 5 && pc[ind] < rv) ind++;
        if (ind > 4) ind = 4;

        int idx = i + offsets[ind];
        if (ind != 0 && idx > 0 && idx < n) {
            int a = p.v[i];
            p.v[i] = p.v[idx];
            p.v[idx] = a;
        }
    }
    return p;
}

__device__ constexpr PermTable g_perm = make_perm();

// ---------------------------------------------------------------------------

__device__ __forceinline__ uint64_t mk_policy_evict_last() {
    uint64_t pol;
    asm("createpolicy.fractional.L2::evict_last.L2::evict_first.b64 %0, 0.85;"
        : "=l"(pol));
    return pol;
}

__device__ __forceinline__ void cp_async16_pol(uint32_t saddr, const void* g,
                                               uint64_t pol) {
    asm volatile("cp.async.cg.shared.global.L2::cache_hint [%0], [%1], 16, %2;\n"
                 :: "r"(saddr), "l"(g), "l"(pol) : "memory");
}
__device__ __forceinline__ void cp_commit() {
    asm volatile("cp.async.commit_group;\n" ::: "memory");
}
template <int N>
__device__ __forceinline__ void cp_wait() {
    asm volatile("cp.async.wait_group %0;\n" :: "n"(N) : "memory");
}

__device__ __forceinline__ void load_row_async(
    uint32_t buf_saddr, const float* __restrict__ xrow, int t, uint64_t pol)
{
    #pragma unroll
    for (int k = 0; k < VECS_PER_THR; ++k) {
        int v = t + k * NTHR;
        if (v < NVEC) {
            cp_async16_pol(buf_saddr + (uint32_t)v * 16u,
                           reinterpret_cast<const float4*>(xrow) + v, pol);
        }
    }
    cp_commit();
}

extern __shared__ float s_buf[];   // NSTAGE * N_ELEM floats = 112896 B

__global__ __launch_bounds__(NTHR) void clop_gather_kernel(
    const float* __restrict__ x, float* __restrict__ out, int nrows)
{
    const int t = threadIdx.x;
    const int r0 = blockIdx.x * ROWS_PER_BLK;
    const uint64_t pol = mk_policy_evict_last();

    uint32_t sa0;
    asm("{ .reg .u64 a; cvta.to.shared.u64 a, %1; cvt.u32.u64 %0, a; }"
        : "=r"(sa0) : "l"(s_buf));

    // prologue: issue rows r0, r0+1, r0+2 into stages 0,1,2
    #pragma unroll
    for (int q = 0; q < NSTAGE - 1; ++q) {
        int row = r0 + q;
        if (row < nrows)
            load_row_async(sa0 + (uint32_t)q * (N_ELEM * 4u),
                           x + (size_t)row * N_ELEM, t, pol);
        else
            cp_commit();   // keep group counts aligned across threads
    }

    // perm values for this thread's columns (coalesced LDG, once per block;
    // overlapped under the prologue's DRAM latency)
    const int* __restrict__ pg = g_perm.v;
    int pc[COLS_PER_THR];
    #pragma unroll
    for (int k = 0; k < COLS_PER_THR; ++k) {
        int col = t + k * NTHR;
        pc[k] = (col < N_ELEM) ? __ldg(pg + col) : 0;
    }

    #pragma unroll
    for (int r = 0; r < ROWS_PER_BLK; ++r) {
        int row = r0 + r;
        if (row >= nrows) break;

        // issue row r+3 into the stage being vacated (its last reader was row
        // r-1, whose scatter finished at the end-of-iter barrier), then wait
        // until row r's group is complete.
        if (r + NSTAGE - 1 < ROWS_PER_BLK) {
            int nrow = row + NSTAGE - 1;
            if (nrow < nrows)
                load_row_async(sa0 + (uint32_t)((r + NSTAGE - 1) & (NSTAGE - 1)) * (N_ELEM * 4u),
                               x + (size_t)nrow * N_ELEM, t, pol);
            else
                cp_commit();
            cp_wait<NSTAGE - 1>();
        } else if (r + NSTAGE - 1 == ROWS_PER_BLK) {
            cp_wait<NSTAGE - 2>();
        } else if (r + NSTAGE - 2 == ROWS_PER_BLK) {
            cp_wait<NSTAGE - 3>();
        } else {
            cp_wait<0>();
        }
        __syncthreads();

        const float* cur = s_buf + (size_t)(r & (NSTAGE - 1)) * N_ELEM;

        // permuted read from smem (stride-1 => conflict-free), coalesced
        // streaming scalar stores
        float* dst = out + (size_t)row * N_ELEM;
        #pragma unroll
        for (int k = 0; k < COLS_PER_THR; ++k) {
            int col = t + k * NTHR;
            if (col < N_ELEM) __stcs(dst + col, cur[pc[k]]);
        }
        __syncthreads();  // all reads of 'cur' done before its stage refills
    }
}

// ---------------------------------------------------------------------------

extern "C" void kernel_launch(void* const* d_in, const int* in_sizes, int n_in,
                              void* d_out, int out_size) {
    const float* x = (const float*)d_in[0];
    float* out = (float*)d_out;
    int total = in_sizes[0];
    int nrows = total / N_ELEM;    // 512*9 = 4608

    const int smem_bytes = NSTAGE * N_ELEM * (int)sizeof(float);   // 112896
    cudaFuncSetAttribute(clop_gather_kernel,
                         cudaFuncAttributeMaxDynamicSharedMemorySize,
                         smem_bytes);

    int nblk = (nrows + ROWS_PER_BLK - 1) / ROWS_PER_BLK;   // 288
    clop_gather_kernel<<<nblk, NTHR, smem_bytes>>>(x, out, nrows);
}

// round 10
// speedup vs baseline: 1.4322x; 1.0075x over previous
#include <cuda_runtime.h>
#include <cuda_bf16.h>
#include <cstdint>

// ---------------------------------------------------------------------------
// CLOPLayer: out[b,c,j] = x[b,c,perm[j]], perm = fixed JAX threefry(42)
// neighbor-swap permutation, evaluated at COMPILE TIME (constexpr) and baked
// into module .data. Single-kernel graph.
// Wall is pinned at the sustained mixed R/W DRAM ceiling (~5.4TB/s, DRAM
// busy 67%). This round targets the ceiling itself: writes leave as 28KB
// LINEAR TMA bulk stores (cp.async.bulk.global.shared) instead of per-warp
// STG sectors, giving the memory controller long same-direction write runs
// (fewer R/W turnarounds). Scatter is smem->smem (stride-1 LDS + STS,
// conflict-free), double-buffered in and out. Reads keep LDGSTS double
// buffering. 288 CTAs x 16 rows, 2 CTAs/SM, one wave.
// ---------------------------------------------------------------------------

#define N_ELEM 7056            // 84*84
#define DIM    84
#define NVEC   (N_ELEM / 4)    // 1764
#define NTHR   512
#define COLS_PER_THR 14        // ceil(7056/512)
#define VECS_PER_THR 4         // ceil(1764/512)
#define ROWS_PER_BLK 16
#define ROW_BYTES (N_ELEM * 4) // 28224

// ---------------------------------------------------------------------------
// Compile-time bit-exact JAX RNG replication (threefry2x32, partitionable)
// ---------------------------------------------------------------------------

struct PermTable { int v[N_ELEM]; };

constexpr uint32_t rotl32c(uint32_t v, int r) {
    return (v << r) | (v >> (32 - r));
}

struct TF2 { uint32_t x0, x1; };

constexpr TF2 threefry2x32c(uint32_t k0, uint32_t k1, uint32_t x0, uint32_t x1) {
    const uint32_t ks0 = k0;
    const uint32_t ks1 = k1;
    const uint32_t ks2 = k0 ^ k1 ^ 0x1BD11BDAu;
    const int ra[4] = {13, 15, 26, 6};
    const int rb[4] = {17, 29, 16, 24};

    x0 += ks0; x1 += ks1;
    for (int i = 0; i < 4; i++) { x0 += x1; x1 = rotl32c(x1, ra[i]); x1 ^= x0; }
    x0 += ks1; x1 += ks2 + 1u;
    for (int i = 0; i < 4; i++) { x0 += x1; x1 = rotl32c(x1, rb[i]); x1 ^= x0; }
    x0 += ks2; x1 += ks0 + 2u;
    for (int i = 0; i < 4; i++) { x0 += x1; x1 = rotl32c(x1, ra[i]); x1 ^= x0; }
    x0 += ks0; x1 += ks1 + 3u;
    for (int i = 0; i < 4; i++) { x0 += x1; x1 = rotl32c(x1, rb[i]); x1 ^= x0; }
    x0 += ks1; x1 += ks2 + 4u;
    for (int i = 0; i < 4; i++) { x0 += x1; x1 = rotl32c(x1, ra[i]); x1 ^= x0; }
    x0 += ks2; x1 += ks0 + 5u;
    return TF2{x0, x1};
}

constexpr uint32_t jax_bits32c(uint32_t k0, uint32_t k1, uint64_t i) {
    TF2 r = threefry2x32c(k0, k1, (uint32_t)(i >> 32), (uint32_t)(i & 0xFFFFFFFFu));
    return r.x0 ^ r.x1;
}

constexpr PermTable make_perm() {
    PermTable p{};
    const int n = N_ELEM;
    const int dim = DIM;
    const int steps = 2 * n - 1;   // 14111

    float probs0 = (float)(1.0 - 0.9 / 2.0);
    float probsq = (float)(0.9 / 8.0);
    float pc[5] = {};
    pc[0] = probs0;
    for (int q = 1; q < 5; q++) pc[q] = pc[q - 1] + probsq;

    const int offsets[5] = {0, 1, -1, dim, -dim};

    for (int t = 0; t < n; t++) p.v[t] = t;

    const uint32_t k0 = 0u, k1 = 42u;   // jax.random.key(42)

    for (int s = 0; s < steps; s++) {
        int i = s - (n - 1);
        if (i < 0) i = -i;

        uint32_t bits = jax_bits32c(k0, k1, (uint64_t)s);
        // u = bitcast(bits>>9 | 0x3F800000) - 1.0f == (float)(bits>>9) * 2^-23
        float u = (float)(bits >> 9) * (1.0f / 8388608.0f);

        float rv = pc[4] * (1.0f - u);
        int ind = 0;
        while (ind < 5 && pc[ind] < rv) ind++;
        if (ind > 4) ind = 4;

        int idx = i + offsets[ind];
        if (ind != 0 && idx > 0 && idx < n) {
            int a = p.v[i];
            p.v[i] = p.v[idx];
            p.v[idx] = a;
        }
    }
    return p;
}

__device__ constexpr PermTable g_perm = make_perm();

// ---------------------------------------------------------------------------

__device__ __forceinline__ void cp_async16(uint32_t saddr, const void* g) {
    asm volatile("cp.async.cg.shared.global [%0], [%1], 16;\n"
                 :: "r"(saddr), "l"(g) : "memory");
}
__device__ __forceinline__ void cp_commit() {
    asm volatile("cp.async.commit_group;\n" ::: "memory");
}
template <int N>
__device__ __forceinline__ void cp_wait() {
    asm volatile("cp.async.wait_group %0;\n" :: "n"(N) : "memory");
}

// ---- 1D TMA bulk store: smem -> gmem, per-row linear 28KB ----
__device__ __forceinline__ void bulk_store_row(void* gdst, uint32_t ssrc) {
    asm volatile("cp.async.bulk.global.shared::cta.bulk_group [%0], [%1], %2;\n"
                 :: "l"(gdst), "r"(ssrc), "n"(ROW_BYTES) : "memory");
}
__device__ __forceinline__ void bulk_commit() {
    asm volatile("cp.async.bulk.commit_group;\n" ::: "memory");
}
template <int N>
__device__ __forceinline__ void bulk_wait_read() {
    asm volatile("cp.async.bulk.wait_group.read %0;\n" :: "n"(N) : "memory");
}
template <int N>
__device__ __forceinline__ void bulk_wait() {
    asm volatile("cp.async.bulk.wait_group %0;\n" :: "n"(N) : "memory");
}
__device__ __forceinline__ void fence_proxy_async_cta() {
    asm volatile("fence.proxy.async.shared::cta;\n" ::: "memory");
}

__device__ __forceinline__ void load_row_async(
    uint32_t buf_saddr, const float* __restrict__ xrow, int t)
{
    #pragma unroll
    for (int k = 0; k < VECS_PER_THR; ++k) {
        int v = t + k * NTHR;
        if (v < NVEC) {
            cp_async16(buf_saddr + (uint32_t)v * 16u,
                       reinterpret_cast<const float4*>(xrow) + v);
        }
    }
    cp_commit();
}

extern __shared__ float s_mem[];   // 4 * N_ELEM floats = 112896 B
// layout: in0 | in1 | out0 | out1

__global__ __launch_bounds__(NTHR) void clop_gather_kernel(
    const float* __restrict__ x, float* __restrict__ out, int nrows)
{
    const int t = threadIdx.x;
    const int r0 = blockIdx.x * ROWS_PER_BLK;

    uint32_t s_base;
    asm("{ .reg .u64 a; cvta.to.shared.u64 a, %1; cvt.u32.u64 %0, a; }"
        : "=r"(s_base) : "l"(s_mem));

    float* in_buf[2]  = { s_mem,               s_mem + N_ELEM };
    float* out_buf[2] = { s_mem + 2 * N_ELEM,  s_mem + 3 * N_ELEM };
    uint32_t in_sa[2]  = { s_base,                      s_base + (uint32_t)ROW_BYTES };
    uint32_t out_sa[2] = { s_base + 2u * ROW_BYTES,     s_base + 3u * ROW_BYTES };

    // prologue: start loading row r0 into in0
    if (r0 < nrows)
        load_row_async(in_sa[0], x + (size_t)r0 * N_ELEM, t);

    // perm values for this thread's columns (coalesced LDG, once per block;
    // overlapped under the prologue's DRAM latency)
    const int* __restrict__ pg = g_perm.v;
    int pc[COLS_PER_THR];
    #pragma unroll
    for (int k = 0; k < COLS_PER_THR; ++k) {
        int col = t + k * NTHR;
        pc[k] = (col < N_ELEM) ? __ldg(pg + col) : 0;
    }

    #pragma unroll
    for (int r = 0; r < ROWS_PER_BLK; ++r) {
        int row = r0 + r;
        if (row >= nrows) break;

        // prefetch next row into the other in-buffer (freed by row r-1's
        // scatter, ordered by the end-of-iteration barrier), then wait for
        // row r's loads.
        if (r + 1 < ROWS_PER_BLK && row + 1 < nrows) {
            load_row_async(in_sa[(r + 1) & 1], x + (size_t)(row + 1) * N_ELEM, t);
            cp_wait<1>();
        } else {
            cp_wait<0>();
        }
        // out-buffer (r&1) reuse: row r-2's bulk store must have finished
        // READING smem (allow row r-1's store still pending).
        if (t == 0) bulk_wait_read<1>();
        __syncthreads();

        // scatter smem->smem: permuted LDS (stride-1 => conflict-free),
        // stride-1 STS into the staging out-buffer
        const float* __restrict__ cin = in_buf[r & 1];
        float* __restrict__ cout = out_buf[r & 1];
        #pragma unroll
        for (int k = 0; k < COLS_PER_THR; ++k) {
            int col = t + k * NTHR;
            if (col < N_ELEM) cout[col] = cin[pc[k]];
        }
        __syncthreads();  // out-buffer fully written; in-buffer fully read

        // one thread issues the 28KB linear bulk store for this row
        if (t == 0) {
            fence_proxy_async_cta();
            bulk_store_row(out + (size_t)row * N_ELEM, out_sa[r & 1]);
            bulk_commit();
        }
    }

    // drain outstanding bulk stores before CTA exit
    if (t == 0) bulk_wait<0>();
}

// ---------------------------------------------------------------------------

extern "C" void kernel_launch(void* const* d_in, const int* in_sizes, int n_in,
                              void* d_out, int out_size) {
    const float* x = (const float*)d_in[0];
    float* out = (float*)d_out;
    int total = in_sizes[0];
    int nrows = total / N_ELEM;    // 512*9 = 4608

    const int smem_bytes = 4 * N_ELEM * (int)sizeof(float);   // 112896
    cudaFuncSetAttribute(clop_gather_kernel,
                         cudaFuncAttributeMaxDynamicSharedMemorySize,
                         smem_bytes);

    int nblk = (nrows + ROWS_PER_BLK - 1) / ROWS_PER_BLK;   // 288
    clop_gather_kernel<<<nblk, NTHR, smem_bytes>>>(x, out, nrows);
}